// round 2
// baseline (speedup 1.0000x reference)
#include <cuda_runtime.h>
#include <cstdint>
#include <cstddef>

typedef unsigned long long ull;

#define DEV_INLINE __device__ __forceinline__

DEV_INLINE ull fma2(ull a, ull b, ull c) {
    ull d; asm("fma.rn.f32x2 %0, %1, %2, %3;" : "=l"(d) : "l"(a), "l"(b), "l"(c)); return d;
}
DEV_INLINE ull pack2(float lo, float hi) {
    ull r; asm("mov.b64 %0, {%1, %2};" : "=l"(r) : "f"(lo), "f"(hi)); return r;
}
DEV_INLINE float2 unpk(ull v) {
    float2 f; asm("mov.b64 {%0, %1}, %2;" : "=f"(f.x), "=f"(f.y) : "l"(v)); return f;
}

// ---------------------------------------------------------------------------
// Problem constants
// ---------------------------------------------------------------------------
#define BB 256   // batch
#define TT 512   // time
#define HH 256   // hidden
#define G3 768   // 3*H

// ---------------------------------------------------------------------------
// Scratch (static device arrays; cudaMalloc forbidden)
// ---------------------------------------------------------------------------
__device__ float g_xg[(size_t)BB * TT * G3];    // 402 MB: input-gate preactivations (reused per layer)
__device__ float g_out0[(size_t)BB * TT * HH];  // 134 MB: layer-0 output sequence
__device__ float g_hT[BB * HH];                 // final hidden of layer 1

// ---------------------------------------------------------------------------
// GEMM: C[M][N] = A[M][K] @ W[N][K]^T + bias[N]
// 64x64 tile, BK=16, 256 threads, 4x4 microtile, f32x2 FMAs.
// A stored duplicated {a,a} in smem (no splat MOVs in inner loop),
// B pairs read directly as ull (adjacent n-columns).
// ---------------------------------------------------------------------------
__global__ __launch_bounds__(256) void gemm_tn_bias(
    const float* __restrict__ A, const float* __restrict__ W,
    const float* __restrict__ bias, float* __restrict__ C,
    int M, int N, int K)
{
    __shared__ ull   As2[16][66];   // [k][m] duplicated pairs (stride pad)
    __shared__ float Bs [16][72];   // [k][n] (stride pad, keeps 16B align)

    const int tid = threadIdx.x;
    const int tm = tid >> 4;            // 0..15 -> rows 4*tm..+3
    const int tn = tid & 15;            // 0..15 -> cols 4*tn..+3
    const int mb = blockIdx.x * 64;
    const int nb = blockIdx.y * 64;
    const int lr = tid >> 2;            // load row 0..63
    const int lc = (tid & 3) * 4;       // load col base 0,4,8,12

    ull acc[4][2];
#pragma unroll
    for (int i = 0; i < 4; ++i) { acc[i][0] = 0ull; acc[i][1] = 0ull; }

    for (int k0 = 0; k0 < K; k0 += 16) {
        const float* ap = A + (size_t)(mb + lr) * K + k0 + lc;
        const float* wp = W + (size_t)(nb + lr) * K + k0 + lc;
#pragma unroll
        for (int j = 0; j < 4; ++j) {
            bool ok = (k0 + lc + j) < K;
            float av = ok ? ap[j] : 0.f;
            float wv = ok ? wp[j] : 0.f;
            As2[lc + j][lr] = pack2(av, av);
            Bs [lc + j][lr] = wv;
        }
        __syncthreads();
#pragma unroll
        for (int k = 0; k < 16; ++k) {
            ulonglong2 bv  = *(const ulonglong2*)&Bs[k][4 * tn];
            ulonglong2 a01 = *(const ulonglong2*)&As2[k][4 * tm];
            ulonglong2 a23 = *(const ulonglong2*)&As2[k][4 * tm + 2];
            acc[0][0] = fma2(a01.x, bv.x, acc[0][0]);
            acc[0][1] = fma2(a01.x, bv.y, acc[0][1]);
            acc[1][0] = fma2(a01.y, bv.x, acc[1][0]);
            acc[1][1] = fma2(a01.y, bv.y, acc[1][1]);
            acc[2][0] = fma2(a23.x, bv.x, acc[2][0]);
            acc[2][1] = fma2(a23.x, bv.y, acc[2][1]);
            acc[3][0] = fma2(a23.y, bv.x, acc[3][0]);
            acc[3][1] = fma2(a23.y, bv.y, acc[3][1]);
        }
        __syncthreads();
    }

    float4 bb = *(const float4*)(bias + nb + 4 * tn);
#pragma unroll
    for (int i = 0; i < 4; ++i) {
        float2 p0 = unpk(acc[i][0]);
        float2 p1 = unpk(acc[i][1]);
        float4 o;
        o.x = p0.x + bb.x; o.y = p0.y + bb.y;
        o.z = p1.x + bb.z; o.w = p1.y + bb.w;
        *(float4*)(C + (size_t)(mb + 4 * tm + i) * N + nb + 4 * tn) = o;
    }
}

// ---------------------------------------------------------------------------
// GRU recurrence: clusters of 4 CTAs, 32 independent clusters.
// Each CTA: 64 hidden units x 3 gates (192 W_hh rows resident in smem),
// all 8 cluster batches. h exchanged via DSMEM, 1 cluster.sync per step.
// ---------------------------------------------------------------------------
#define REC_W_FLOATS (192 * 260)                         // padded rows
#define REC_SMEM     ((192 * 260 + 2 * 8 * 260) * 4)     // 216320 B

DEV_INLINE unsigned ctarank() { unsigned r; asm("mov.u32 %0, %%cluster_ctarank;" : "=r"(r)); return r; }
DEV_INLINE void cluster_sync_() {
    asm volatile("barrier.cluster.arrive.aligned;\n\tbarrier.cluster.wait.aligned;" ::: "memory");
}
DEV_INLINE unsigned s2u(const void* p) {
    unsigned a;
    asm("{ .reg .u64 t; cvta.to.shared.u64 t, %1; cvt.u32.u64 %0, t; }" : "=r"(a) : "l"(p));
    return a;
}
DEV_INLINE unsigned mapa_(unsigned a, unsigned r) {
    unsigned o; asm("mapa.shared::cluster.u32 %0, %1, %2;" : "=r"(o) : "r"(a), "r"(r)); return o;
}
DEV_INLINE void st_cluster_u32(unsigned addr, unsigned v) {
    asm volatile("st.shared::cluster.u32 [%0], %1;" :: "r"(addr), "r"(v) : "memory");
}

__global__ __launch_bounds__(256, 1) void gru_rec(
    const float* __restrict__ xg, const float* __restrict__ W_hh,
    const float* __restrict__ b_hh, float* __restrict__ out_seq,
    float* __restrict__ hT, int layer0)
{
    extern __shared__ float smem[];
    float* w = smem;                        // [192 rows][260] (only [0..255] used per row)
    float* hbase = smem + REC_W_FLOATS;     // [2 bufs][8 batches][260]

    const int tid = threadIdx.x;
    const unsigned rank = ctarank();
    const int cid = blockIdx.x >> 2;        // cluster id 0..31
    const int h_local = tid >> 2;           // 0..63
    const int bp = tid & 3;                 // batch-pair 0..3
    const int h_glob = (int)rank * 64 + h_local;
    const int b0 = cid * 8 + bp * 2;

    // Load this CTA's W_hh slice: smem row g*64+h  <-  global row g*256 + rank*64 + h
    for (int i = tid; i < 192 * 64; i += 256) {
        int row = i >> 6, k4 = i & 63;
        int grow = (row >> 6) * 256 + (int)rank * 64 + (row & 63);
        float4 v = ((const float4*)W_hh)[(size_t)grow * 64 + k4];
        *(float4*)(w + row * 260 + k4 * 4) = v;
    }
    // zero h buffer 0 (buffer 1 is fully overwritten in step 0)
    for (int i = tid; i < 8 * 260; i += 256) hbase[i] = 0.f;

    const float bh_r = b_hh[h_glob];
    const float bh_z = b_hh[256 + h_glob];
    const float bh_n = b_hh[512 + h_glob];

    __syncthreads();
    cluster_sync_();

    unsigned hbase_u = s2u(hbase);
    unsigned pb[4];
#pragma unroll
    for (int q = 0; q < 4; ++q) pb[q] = mapa_(hbase_u, (unsigned)q);

    const float* wr = w + h_local * 260;
    const float* wz = w + (64 + h_local) * 260;
    const float* wn = w + (128 + h_local) * 260;

    int p = 0;
    for (int t = 0; t < TT; ++t) {
        // prefetch input-gate preactivations (consumed after the k-loop)
        const float* x0 = xg + ((size_t)b0 * TT + t) * G3;
        const float* x1 = x0 + (size_t)TT * G3;
        float xr0 = x0[h_glob], xz0 = x0[256 + h_glob], xn0 = x0[512 + h_glob];
        float xr1 = x1[h_glob], xz1 = x1[256 + h_glob], xn1 = x1[512 + h_glob];

        const float* h0r = hbase + (p * 8 + bp * 2) * 260;
        const float* h1r = h0r + 260;

        // accumulate even/odd-k partials packed in f32x2
        ull ar0 = 0, az0 = 0, an0 = 0, ar1 = 0, az1 = 0, an1 = 0;
#pragma unroll 4
        for (int k4 = 0; k4 < 64; ++k4) {
            ulonglong2 wrv = *(const ulonglong2*)(wr + 4 * k4);
            ulonglong2 wzv = *(const ulonglong2*)(wz + 4 * k4);
            ulonglong2 wnv = *(const ulonglong2*)(wn + 4 * k4);
            ulonglong2 h0v = *(const ulonglong2*)(h0r + 4 * k4);
            ulonglong2 h1v = *(const ulonglong2*)(h1r + 4 * k4);
            ar0 = fma2(wrv.x, h0v.x, ar0); ar0 = fma2(wrv.y, h0v.y, ar0);
            az0 = fma2(wzv.x, h0v.x, az0); az0 = fma2(wzv.y, h0v.y, az0);
            an0 = fma2(wnv.x, h0v.x, an0); an0 = fma2(wnv.y, h0v.y, an0);
            ar1 = fma2(wrv.x, h1v.x, ar1); ar1 = fma2(wrv.y, h1v.y, ar1);
            az1 = fma2(wzv.x, h1v.x, az1); az1 = fma2(wzv.y, h1v.y, az1);
            an1 = fma2(wnv.x, h1v.x, an1); an1 = fma2(wnv.y, h1v.y, an1);
        }
        float2 s;
        s = unpk(ar0); float hr0 = s.x + s.y;
        s = unpk(az0); float hz0 = s.x + s.y;
        s = unpk(an0); float hn0 = s.x + s.y;
        s = unpk(ar1); float hr1 = s.x + s.y;
        s = unpk(az1); float hz1 = s.x + s.y;
        s = unpk(an1); float hn1 = s.x + s.y;

        float hp0 = h0r[h_glob];
        float hp1 = h1r[h_glob];

        float r0 = 1.f / (1.f + __expf(-(xr0 + bh_r + hr0)));
        float z0 = 1.f / (1.f + __expf(-(xz0 + bh_z + hz0)));
        float n0 = tanhf(xn0 + r0 * (hn0 + bh_n));
        float hnew0 = (1.f - z0) * n0 + z0 * hp0;

        float r1 = 1.f / (1.f + __expf(-(xr1 + bh_r + hr1)));
        float z1 = 1.f / (1.f + __expf(-(xz1 + bh_z + hz1)));
        float n1 = tanhf(xn1 + r1 * (hn1 + bh_n));
        float hnew1 = (1.f - z1) * n1 + z1 * hp1;

        // broadcast h_new to all 4 cluster CTAs (double buffer 1-p)
        unsigned off0 = (unsigned)(((1 - p) * 8 + bp * 2) * 260 + h_glob) * 4u;
        unsigned off1 = off0 + 260u * 4u;
#pragma unroll
        for (int q = 0; q < 4; ++q) {
            st_cluster_u32(pb[q] + off0, __float_as_uint(hnew0));
            st_cluster_u32(pb[q] + off1, __float_as_uint(hnew1));
        }

        if (layer0) {
            out_seq[((size_t)b0 * TT + t) * HH + h_glob]       = hnew0;
            out_seq[((size_t)(b0 + 1) * TT + t) * HH + h_glob] = hnew1;
        } else if (t == TT - 1) {
            hT[b0 * HH + h_glob]       = hnew0;
            hT[(b0 + 1) * HH + h_glob] = hnew1;
        }

        cluster_sync_();
        p ^= 1;
    }
}

// ---------------------------------------------------------------------------
// Launch
// ---------------------------------------------------------------------------
static void launch_rec(const float* xg, const float* Whh, const float* bhh,
                       float* oseq, float* hT, int layer0)
{
    cudaFuncSetAttribute(gru_rec, cudaFuncAttributeMaxDynamicSharedMemorySize, REC_SMEM);
    cudaLaunchConfig_t cfg = {};
    cfg.gridDim = dim3(128, 1, 1);
    cfg.blockDim = dim3(256, 1, 1);
    cfg.dynamicSmemBytes = REC_SMEM;
    cfg.stream = 0;
    cudaLaunchAttribute at[1];
    at[0].id = cudaLaunchAttributeClusterDimension;
    at[0].val.clusterDim.x = 4;
    at[0].val.clusterDim.y = 1;
    at[0].val.clusterDim.z = 1;
    cfg.attrs = at;
    cfg.numAttrs = 1;
    cudaLaunchKernelEx(&cfg, gru_rec, xg, Whh, bhh, oseq, hT, layer0);
}

extern "C" void kernel_launch(void* const* d_in, const int* in_sizes, int n_in,
                              void* d_out, int out_size)
{
    const float* x     = (const float*)d_in[0];
    const float* W_ih0 = (const float*)d_in[1];
    const float* W_hh0 = (const float*)d_in[2];
    const float* b_ih0 = (const float*)d_in[3];
    const float* b_hh0 = (const float*)d_in[4];
    const float* W_ih1 = (const float*)d_in[5];
    const float* W_hh1 = (const float*)d_in[6];
    const float* b_ih1 = (const float*)d_in[7];
    const float* b_hh1 = (const float*)d_in[8];
    const float* fc_W  = (const float*)d_in[9];
    const float* fc_b  = (const float*)d_in[10];
    float* out = (float*)d_out;

    float *xg, *o0, *hT;
    cudaGetSymbolAddress((void**)&xg, g_xg);
    cudaGetSymbolAddress((void**)&o0, g_out0);
    cudaGetSymbolAddress((void**)&hT, g_hT);

    const int M = BB * TT;  // 131072

    // 1) xg0 = x @ W_ih0^T + b_ih0   (K = 75)
    gemm_tn_bias<<<dim3(M / 64, G3 / 64), 256>>>(x, W_ih0, b_ih0, xg, M, G3, 75);
    // 2) layer-0 recurrence -> out0 sequence
    launch_rec(xg, W_hh0, b_hh0, o0, nullptr, 1);
    // 3) xg1 = out0 @ W_ih1^T + b_ih1  (K = 256)
    gemm_tn_bias<<<dim3(M / 64, G3 / 64), 256>>>(o0, W_ih1, b_ih1, xg, M, G3, 256);
    // 4) layer-1 recurrence -> final hidden
    launch_rec(xg, W_hh1, b_hh1, nullptr, hT, 0);
    // 5) embedding = hT @ fc_W^T + fc_b
    gemm_tn_bias<<<dim3(BB / 64, HH / 64), 256>>>(hT, fc_W, fc_b, out, BB, HH, HH);
}

// round 4
// speedup vs baseline: 1.0282x; 1.0282x over previous
#include <cuda_runtime.h>
#include <cstdint>
#include <cstddef>

typedef unsigned long long ull;

#define DEV_INLINE __device__ __forceinline__

DEV_INLINE ull fma2(ull a, ull b, ull c) {
    ull d; asm("fma.rn.f32x2 %0, %1, %2, %3;" : "=l"(d) : "l"(a), "l"(b), "l"(c)); return d;
}
DEV_INLINE ull pack2(float lo, float hi) {
    ull r; asm("mov.b64 %0, {%1, %2};" : "=l"(r) : "f"(lo), "f"(hi)); return r;
}
DEV_INLINE float2 unpk(ull v) {
    float2 f; asm("mov.b64 {%0, %1}, %2;" : "=f"(f.x), "=f"(f.y) : "l"(v)); return f;
}

// ---------------------------------------------------------------------------
// Problem constants
// ---------------------------------------------------------------------------
#define BB 256   // batch
#define TT 512   // time
#define HH 256   // hidden
#define G3 768   // 3*H

// ---------------------------------------------------------------------------
// Scratch (static device arrays; cudaMalloc forbidden)
// ---------------------------------------------------------------------------
__device__ float g_xg[(size_t)BB * TT * G3];    // input-gate preactivations (reused per layer)
__device__ float g_out0[(size_t)BB * TT * HH];  // layer-0 output sequence
__device__ float g_hT[BB * HH];                 // final hidden of layer 1

// ---------------------------------------------------------------------------
// GEMM: C[M][N] = A[M][K] @ W[N][K]^T + bias[N]
// 128x128 tile, BK=16, 256 threads, 8x8 microtile, f32x2 FMAs.
// Vector (float4) global loads ONLY when K % 4 == 0 (alignment!);
// scalar fill otherwise (K=75 case).
// ---------------------------------------------------------------------------
__global__ __launch_bounds__(256, 2) void gemm_tn_bias(
    const float* __restrict__ A, const float* __restrict__ W,
    const float* __restrict__ bias, float* __restrict__ C,
    int M, int N, int K)
{
    __shared__ ull As2[16][130];  // [k][m-row] duplicated pairs
    __shared__ ull Bs2[16][68];   // [k][n-pair]

    const int tid = threadIdx.x;
    const int tm = tid >> 4;          // 0..15 -> rows 8*tm..+7
    const int tn = tid & 15;          // 0..15 -> pairs tn+16*j
    const int mb = blockIdx.x * 128;
    const int nb = blockIdx.y * 128;

    const int lr = tid >> 1;          // 0..127 A-row
    const int lh = (tid & 1) * 8;     // A k-offset 0/8
    const int pp = tid >> 2;          // 0..63 B-pair
    const int pq = (tid & 3) * 4;     // B k-offset 0,4,8,12

    const bool kvec = ((K & 3) == 0);   // float4 loads legal only then

    ull acc[8][4];
#pragma unroll
    for (int i = 0; i < 8; ++i)
#pragma unroll
        for (int j = 0; j < 4; ++j) acc[i][j] = 0ull;

    for (int k0 = 0; k0 < K; k0 += 16) {
        // ---- fill A tile ----
        const float* ap = A + (size_t)(mb + lr) * K + k0 + lh;
        if (kvec && k0 + 16 <= K) {
            float4 v0 = *(const float4*)(ap);
            float4 v1 = *(const float4*)(ap + 4);
            As2[lh + 0][lr] = pack2(v0.x, v0.x);
            As2[lh + 1][lr] = pack2(v0.y, v0.y);
            As2[lh + 2][lr] = pack2(v0.z, v0.z);
            As2[lh + 3][lr] = pack2(v0.w, v0.w);
            As2[lh + 4][lr] = pack2(v1.x, v1.x);
            As2[lh + 5][lr] = pack2(v1.y, v1.y);
            As2[lh + 6][lr] = pack2(v1.z, v1.z);
            As2[lh + 7][lr] = pack2(v1.w, v1.w);
        } else {
#pragma unroll
            for (int j = 0; j < 8; ++j) {
                float v = (k0 + lh + j < K) ? ap[j] : 0.f;
                As2[lh + j][lr] = pack2(v, v);
            }
        }
        // ---- fill B tile (pack adjacent n-rows into pairs) ----
        const float* wp0 = W + (size_t)(nb + 2 * pp) * K + k0 + pq;
        const float* wp1 = wp0 + K;
        if (kvec && k0 + 16 <= K) {
            float4 w0 = *(const float4*)wp0;
            float4 w1 = *(const float4*)wp1;
            Bs2[pq + 0][pp] = pack2(w0.x, w1.x);
            Bs2[pq + 1][pp] = pack2(w0.y, w1.y);
            Bs2[pq + 2][pp] = pack2(w0.z, w1.z);
            Bs2[pq + 3][pp] = pack2(w0.w, w1.w);
        } else {
#pragma unroll
            for (int j = 0; j < 4; ++j) {
                bool ok = (k0 + pq + j < K);
                Bs2[pq + j][pp] = pack2(ok ? wp0[j] : 0.f, ok ? wp1[j] : 0.f);
            }
        }
        __syncthreads();
#pragma unroll
        for (int k = 0; k < 16; ++k) {
            ulonglong2 a01 = *(const ulonglong2*)&As2[k][8 * tm];
            ulonglong2 a23 = *(const ulonglong2*)&As2[k][8 * tm + 2];
            ulonglong2 a45 = *(const ulonglong2*)&As2[k][8 * tm + 4];
            ulonglong2 a67 = *(const ulonglong2*)&As2[k][8 * tm + 6];
            ull b0 = Bs2[k][tn];
            ull b1 = Bs2[k][16 + tn];
            ull b2 = Bs2[k][32 + tn];
            ull b3 = Bs2[k][48 + tn];
            acc[0][0] = fma2(a01.x, b0, acc[0][0]); acc[0][1] = fma2(a01.x, b1, acc[0][1]);
            acc[0][2] = fma2(a01.x, b2, acc[0][2]); acc[0][3] = fma2(a01.x, b3, acc[0][3]);
            acc[1][0] = fma2(a01.y, b0, acc[1][0]); acc[1][1] = fma2(a01.y, b1, acc[1][1]);
            acc[1][2] = fma2(a01.y, b2, acc[1][2]); acc[1][3] = fma2(a01.y, b3, acc[1][3]);
            acc[2][0] = fma2(a23.x, b0, acc[2][0]); acc[2][1] = fma2(a23.x, b1, acc[2][1]);
            acc[2][2] = fma2(a23.x, b2, acc[2][2]); acc[2][3] = fma2(a23.x, b3, acc[2][3]);
            acc[3][0] = fma2(a23.y, b0, acc[3][0]); acc[3][1] = fma2(a23.y, b1, acc[3][1]);
            acc[3][2] = fma2(a23.y, b2, acc[3][2]); acc[3][3] = fma2(a23.y, b3, acc[3][3]);
            acc[4][0] = fma2(a45.x, b0, acc[4][0]); acc[4][1] = fma2(a45.x, b1, acc[4][1]);
            acc[4][2] = fma2(a45.x, b2, acc[4][2]); acc[4][3] = fma2(a45.x, b3, acc[4][3]);
            acc[5][0] = fma2(a45.y, b0, acc[5][0]); acc[5][1] = fma2(a45.y, b1, acc[5][1]);
            acc[5][2] = fma2(a45.y, b2, acc[5][2]); acc[5][3] = fma2(a45.y, b3, acc[5][3]);
            acc[6][0] = fma2(a67.x, b0, acc[6][0]); acc[6][1] = fma2(a67.x, b1, acc[6][1]);
            acc[6][2] = fma2(a67.x, b2, acc[6][2]); acc[6][3] = fma2(a67.x, b3, acc[6][3]);
            acc[7][0] = fma2(a67.y, b0, acc[7][0]); acc[7][1] = fma2(a67.y, b1, acc[7][1]);
            acc[7][2] = fma2(a67.y, b2, acc[7][2]); acc[7][3] = fma2(a67.y, b3, acc[7][3]);
        }
        __syncthreads();
    }

    // epilogue: pairs at columns 2*(tn+16j), 2*(tn+16j)+1
    float2 bb[4];
#pragma unroll
    for (int j = 0; j < 4; ++j)
        bb[j] = *(const float2*)(bias + nb + 2 * (tn + 16 * j));
#pragma unroll
    for (int i = 0; i < 8; ++i) {
        float* crow = C + (size_t)(mb + 8 * tm + i) * N + nb;
#pragma unroll
        for (int j = 0; j < 4; ++j) {
            float2 v = unpk(acc[i][j]);
            v.x += bb[j].x; v.y += bb[j].y;
            *(float2*)(crow + 2 * (tn + 16 * j)) = v;
        }
    }
}

// ---------------------------------------------------------------------------
// GRU recurrence: 32 clusters x 4 CTAs. Each CTA: 64 hidden x 3 gates
// (192 W_hh rows in smem), 512 threads = 64 h x 8 batches (1 batch/thread).
// h exchanged via DSMEM push; split cluster arrive/wait hides sync + DRAM.
// ---------------------------------------------------------------------------
#define REC_W_FLOATS (192 * 260)
#define REC_SMEM     ((192 * 260 + 2 * 8 * 260) * 4)   // 216320 B

DEV_INLINE unsigned ctarank() { unsigned r; asm("mov.u32 %0, %%cluster_ctarank;" : "=r"(r)); return r; }
DEV_INLINE unsigned s2u(const void* p) {
    unsigned a;
    asm("{ .reg .u64 t; cvta.to.shared.u64 t, %1; cvt.u32.u64 %0, t; }" : "=r"(a) : "l"(p));
    return a;
}
DEV_INLINE unsigned mapa_(unsigned a, unsigned r) {
    unsigned o; asm("mapa.shared::cluster.u32 %0, %1, %2;" : "=r"(o) : "r"(a), "r"(r)); return o;
}
DEV_INLINE void st_cluster_u32(unsigned addr, unsigned v) {
    asm volatile("st.shared::cluster.u32 [%0], %1;" :: "r"(addr), "r"(v) : "memory");
}
DEV_INLINE void cl_arrive() { asm volatile("barrier.cluster.arrive.aligned;" ::: "memory"); }
DEV_INLINE void cl_wait()   { asm volatile("barrier.cluster.wait.aligned;"   ::: "memory"); }

__global__ __launch_bounds__(512, 1) void gru_rec(
    const float* __restrict__ xg, const float* __restrict__ W_hh,
    const float* __restrict__ b_hh, float* __restrict__ out_seq,
    float* __restrict__ hT, int layer0)
{
    extern __shared__ float smem[];
    float* w = smem;                        // [192 rows][260]
    float* hbase = smem + REC_W_FLOATS;     // [2 bufs][8 batches][260]

    const int tid = threadIdx.x;
    const unsigned rank = ctarank();
    const int cid = blockIdx.x >> 2;        // cluster id 0..31
    const int h_local = tid >> 3;           // 0..63
    const int b = tid & 7;                  // 0..7
    const int h_glob = (int)rank * 64 + h_local;
    const int bglob = cid * 8 + b;

    // Load W_hh slice: smem row g*64+h  <-  global row g*256 + rank*64 + h
    for (int i = tid; i < 192 * 64; i += 512) {
        int row = i >> 6, k4 = i & 63;
        int grow = (row >> 6) * 256 + (int)rank * 64 + (row & 63);
        float4 v = ((const float4*)W_hh)[(size_t)grow * 64 + k4];
        *(float4*)(w + row * 260 + k4 * 4) = v;
    }
    for (int i = tid; i < 8 * 260; i += 512) hbase[i] = 0.f;  // h buffer 0 = 0

    const float bh_r = b_hh[h_glob];
    const float bh_z = b_hh[256 + h_glob];
    const float bh_n = b_hh[512 + h_glob];

    __syncthreads();
    cl_arrive(); cl_wait();

    unsigned hbase_u = s2u(hbase);
    unsigned pb[4];
#pragma unroll
    for (int q = 0; q < 4; ++q) pb[q] = mapa_(hbase_u, (unsigned)q);

    const float* wr = w + h_local * 260;
    const float* wz = wr + 64 * 260;
    const float* wn = wr + 128 * 260;

    const float* xrow = xg + (size_t)bglob * TT * G3;
    // prefetch x for t=0
    float xr = xrow[h_glob], xz = xrow[256 + h_glob], xn = xrow[512 + h_glob];

    int p = 0;
    for (int t = 0; t < TT; ++t) {
        const float* hr_ = hbase + (p * 8 + b) * 260;

        ull ar = 0, az = 0, an = 0;
#pragma unroll 8
        for (int k4 = 0; k4 < 64; ++k4) {
            ulonglong2 hv  = *(const ulonglong2*)(hr_ + 4 * k4);
            ulonglong2 wrv = *(const ulonglong2*)(wr + 4 * k4);
            ulonglong2 wzv = *(const ulonglong2*)(wz + 4 * k4);
            ulonglong2 wnv = *(const ulonglong2*)(wn + 4 * k4);
            ar = fma2(wrv.x, hv.x, ar); ar = fma2(wrv.y, hv.y, ar);
            az = fma2(wzv.x, hv.x, az); az = fma2(wzv.y, hv.y, az);
            an = fma2(wnv.x, hv.x, an); an = fma2(wnv.y, hv.y, an);
        }
        float2 s;
        s = unpk(ar); float hr = s.x + s.y;
        s = unpk(az); float hz = s.x + s.y;
        s = unpk(an); float hn = s.x + s.y;
        float hp = hr_[h_glob];

        float r = 1.f / (1.f + __expf(-(xr + bh_r + hr)));
        float z = 1.f / (1.f + __expf(-(xz + bh_z + hz)));
        float n = tanhf(xn + r * (hn + bh_n));
        float hnew = (1.f - z) * n + z * hp;

        // broadcast h_new to all 4 cluster CTAs (buffer 1-p)
        unsigned off = (unsigned)(((1 - p) * 8 + b) * 260 + h_glob) * 4u;
        unsigned hb = __float_as_uint(hnew);
        st_cluster_u32(pb[0] + off, hb);
        st_cluster_u32(pb[1] + off, hb);
        st_cluster_u32(pb[2] + off, hb);
        st_cluster_u32(pb[3] + off, hb);

        cl_arrive();

        // overlap with barrier: prefetch next x, write output
        if (t + 1 < TT) {
            const float* xp = xrow + (size_t)(t + 1) * G3;
            xr = xp[h_glob]; xz = xp[256 + h_glob]; xn = xp[512 + h_glob];
        }
        if (layer0) {
            out_seq[((size_t)bglob * TT + t) * HH + h_glob] = hnew;
        } else if (t == TT - 1) {
            hT[bglob * HH + h_glob] = hnew;
        }

        cl_wait();
        p ^= 1;
    }
}

// ---------------------------------------------------------------------------
// Launch helpers
// ---------------------------------------------------------------------------
static void launch_rec(const float* xg, const float* Whh, const float* bhh,
                       float* oseq, float* hT, int layer0)
{
    cudaFuncSetAttribute(gru_rec, cudaFuncAttributeMaxDynamicSharedMemorySize, REC_SMEM);
    cudaLaunchConfig_t cfg = {};
    cfg.gridDim = dim3(128, 1, 1);
    cfg.blockDim = dim3(512, 1, 1);
    cfg.dynamicSmemBytes = REC_SMEM;
    cfg.stream = 0;
    cudaLaunchAttribute at[1];
    at[0].id = cudaLaunchAttributeClusterDimension;
    at[0].val.clusterDim.x = 4;
    at[0].val.clusterDim.y = 1;
    at[0].val.clusterDim.z = 1;
    cfg.attrs = at;
    cfg.numAttrs = 1;
    cudaLaunchKernelEx(&cfg, gru_rec, xg, Whh, bhh, oseq, hT, layer0);
}

extern "C" void kernel_launch(void* const* d_in, const int* in_sizes, int n_in,
                              void* d_out, int out_size)
{
    const float* x     = (const float*)d_in[0];
    const float* W_ih0 = (const float*)d_in[1];
    const float* W_hh0 = (const float*)d_in[2];
    const float* b_ih0 = (const float*)d_in[3];
    const float* b_hh0 = (const float*)d_in[4];
    const float* W_ih1 = (const float*)d_in[5];
    const float* W_hh1 = (const float*)d_in[6];
    const float* b_ih1 = (const float*)d_in[7];
    const float* b_hh1 = (const float*)d_in[8];
    const float* fc_W  = (const float*)d_in[9];
    const float* fc_b  = (const float*)d_in[10];
    float* out = (float*)d_out;

    float *xg, *o0, *hT;
    cudaGetSymbolAddress((void**)&xg, g_xg);
    cudaGetSymbolAddress((void**)&o0, g_out0);
    cudaGetSymbolAddress((void**)&hT, g_hT);

    const int M = BB * TT;  // 131072

    // 1) xg0 = x @ W_ih0^T + b_ih0   (K = 75)
    gemm_tn_bias<<<dim3(M / 128, G3 / 128), 256>>>(x, W_ih0, b_ih0, xg, M, G3, 75);
    // 2) layer-0 recurrence -> out0 sequence
    launch_rec(xg, W_hh0, b_hh0, o0, nullptr, 1);
    // 3) xg1 = out0 @ W_ih1^T + b_ih1  (K = 256)
    gemm_tn_bias<<<dim3(M / 128, G3 / 128), 256>>>(o0, W_ih1, b_ih1, xg, M, G3, 256);
    // 4) layer-1 recurrence -> final hidden
    launch_rec(xg, W_hh1, b_hh1, nullptr, hT, 0);
    // 5) embedding = hT @ fc_W^T + fc_b
    gemm_tn_bias<<<dim3(BB / 128, HH / 128), 256>>>(hT, fc_W, fc_b, out, BB, HH, HH);
}

// round 5
// speedup vs baseline: 1.2550x; 1.2205x over previous
#include <cuda_runtime.h>
#include <cstdint>
#include <cstddef>

typedef unsigned long long ull;

#define DEV_INLINE __device__ __forceinline__

DEV_INLINE ull fma2(ull a, ull b, ull c) {
    ull d; asm("fma.rn.f32x2 %0, %1, %2, %3;" : "=l"(d) : "l"(a), "l"(b), "l"(c)); return d;
}
DEV_INLINE ull pack2(float lo, float hi) {
    ull r; asm("mov.b64 %0, {%1, %2};" : "=l"(r) : "f"(lo), "f"(hi)); return r;
}
DEV_INLINE float2 unpk(ull v) {
    float2 f; asm("mov.b64 {%0, %1}, %2;" : "=f"(f.x), "=f"(f.y) : "l"(v)); return f;
}

// ---------------------------------------------------------------------------
// Problem constants
// ---------------------------------------------------------------------------
#define BB 256   // batch
#define TT 512   // time
#define HH 256   // hidden
#define G3 768   // 3*H
#define KP 80    // padded IN_DIM (75 -> 80)

// ---------------------------------------------------------------------------
// Scratch (static device arrays; cudaMalloc forbidden)
// ---------------------------------------------------------------------------
__device__ float g_xg[(size_t)BB * TT * G3];    // input-gate preactivations
__device__ float g_out0[(size_t)BB * TT * HH];  // layer-0 output sequence
__device__ float g_hT[BB * HH];                 // final hidden of layer 1
__device__ float g_xpad[(size_t)BB * TT * KP];  // x padded to K=80
__device__ float g_wpad[G3 * KP];               // W_ih0 padded to K=80

// ---------------------------------------------------------------------------
// Padding pre-kernels (x: [B*T,75] -> [B*T,80]; W_ih0: [768,75] -> [768,80])
// ---------------------------------------------------------------------------
__global__ void pad_k75(const float* __restrict__ src, float* __restrict__ dst, int rows)
{
    int idx = blockIdx.x * blockDim.x + threadIdx.x;
    if (idx >= rows * KP) return;
    int r = idx / KP, c = idx - r * KP;
    dst[idx] = (c < 75) ? src[r * 75 + c] : 0.f;
}

// ---------------------------------------------------------------------------
// GEMM: C[M][N] = A[M][K] @ W[N][K]^T + bias[N]   (K % 4 == 0 required)
// 128x128 tile, BK=16, 256 threads, 8x8 microtile, f32x2 FMAs.
// A duplicated {a,a}; B packed as adjacent-n pairs, loaded 2 pairs per LDS.128.
// Thread (tm,tn): rows 8tm..+7, cols [4tn..4tn+3] and [64+4tn..64+4tn+3].
// ---------------------------------------------------------------------------
__global__ __launch_bounds__(256, 2) void gemm_tn_bias(
    const float* __restrict__ A, const float* __restrict__ W,
    const float* __restrict__ bias, float* __restrict__ C,
    int M, int N, int K)
{
    __shared__ ull As2[16][130];  // [k][m-row] duplicated pairs
    __shared__ ull Bs2[16][68];   // [k][n-pair]

    const int tid = threadIdx.x;
    const int tm = tid >> 4;          // 0..15
    const int tn = tid & 15;          // 0..15
    const int mb = blockIdx.x * 128;
    const int nb = blockIdx.y * 128;

    const int lr = tid >> 1;          // 0..127 A-row
    const int lh = (tid & 1) * 8;     // A k-offset 0/8
    const int pp = tid >> 2;          // 0..63 B-pair
    const int pq = (tid & 3) * 4;     // B k-offset 0,4,8,12

    ull acc[8][4];
#pragma unroll
    for (int i = 0; i < 8; ++i)
#pragma unroll
        for (int j = 0; j < 4; ++j) acc[i][j] = 0ull;

    for (int k0 = 0; k0 < K; k0 += 16) {
        // fill A tile
        const float* ap = A + (size_t)(mb + lr) * K + k0 + lh;
        float4 v0 = *(const float4*)(ap);
        float4 v1 = *(const float4*)(ap + 4);
        As2[lh + 0][lr] = pack2(v0.x, v0.x);
        As2[lh + 1][lr] = pack2(v0.y, v0.y);
        As2[lh + 2][lr] = pack2(v0.z, v0.z);
        As2[lh + 3][lr] = pack2(v0.w, v0.w);
        As2[lh + 4][lr] = pack2(v1.x, v1.x);
        As2[lh + 5][lr] = pack2(v1.y, v1.y);
        As2[lh + 6][lr] = pack2(v1.z, v1.z);
        As2[lh + 7][lr] = pack2(v1.w, v1.w);
        // fill B tile (adjacent n-rows -> pair)
        const float* wp0 = W + (size_t)(nb + 2 * pp) * K + k0 + pq;
        const float* wp1 = wp0 + K;
        float4 w0 = *(const float4*)wp0;
        float4 w1 = *(const float4*)wp1;
        Bs2[pq + 0][pp] = pack2(w0.x, w1.x);
        Bs2[pq + 1][pp] = pack2(w0.y, w1.y);
        Bs2[pq + 2][pp] = pack2(w0.z, w1.z);
        Bs2[pq + 3][pp] = pack2(w0.w, w1.w);
        __syncthreads();
#pragma unroll
        for (int k = 0; k < 16; ++k) {
            ulonglong2 a01 = *(const ulonglong2*)&As2[k][8 * tm];
            ulonglong2 a23 = *(const ulonglong2*)&As2[k][8 * tm + 2];
            ulonglong2 a45 = *(const ulonglong2*)&As2[k][8 * tm + 4];
            ulonglong2 a67 = *(const ulonglong2*)&As2[k][8 * tm + 6];
            ulonglong2 b01 = *(const ulonglong2*)&Bs2[k][2 * tn];
            ulonglong2 b23 = *(const ulonglong2*)&Bs2[k][32 + 2 * tn];
            ull b0 = b01.x, b1 = b01.y, b2 = b23.x, b3 = b23.y;
            acc[0][0] = fma2(a01.x, b0, acc[0][0]); acc[0][1] = fma2(a01.x, b1, acc[0][1]);
            acc[0][2] = fma2(a01.x, b2, acc[0][2]); acc[0][3] = fma2(a01.x, b3, acc[0][3]);
            acc[1][0] = fma2(a01.y, b0, acc[1][0]); acc[1][1] = fma2(a01.y, b1, acc[1][1]);
            acc[1][2] = fma2(a01.y, b2, acc[1][2]); acc[1][3] = fma2(a01.y, b3, acc[1][3]);
            acc[2][0] = fma2(a23.x, b0, acc[2][0]); acc[2][1] = fma2(a23.x, b1, acc[2][1]);
            acc[2][2] = fma2(a23.x, b2, acc[2][2]); acc[2][3] = fma2(a23.x, b3, acc[2][3]);
            acc[3][0] = fma2(a23.y, b0, acc[3][0]); acc[3][1] = fma2(a23.y, b1, acc[3][1]);
            acc[3][2] = fma2(a23.y, b2, acc[3][2]); acc[3][3] = fma2(a23.y, b3, acc[3][3]);
            acc[4][0] = fma2(a45.x, b0, acc[4][0]); acc[4][1] = fma2(a45.x, b1, acc[4][1]);
            acc[4][2] = fma2(a45.x, b2, acc[4][2]); acc[4][3] = fma2(a45.x, b3, acc[4][3]);
            acc[5][0] = fma2(a45.y, b0, acc[5][0]); acc[5][1] = fma2(a45.y, b1, acc[5][1]);
            acc[5][2] = fma2(a45.y, b2, acc[5][2]); acc[5][3] = fma2(a45.y, b3, acc[5][3]);
            acc[6][0] = fma2(a67.x, b0, acc[6][0]); acc[6][1] = fma2(a67.x, b1, acc[6][1]);
            acc[6][2] = fma2(a67.x, b2, acc[6][2]); acc[6][3] = fma2(a67.x, b3, acc[6][3]);
            acc[7][0] = fma2(a67.y, b0, acc[7][0]); acc[7][1] = fma2(a67.y, b1, acc[7][1]);
            acc[7][2] = fma2(a67.y, b2, acc[7][2]); acc[7][3] = fma2(a67.y, b3, acc[7][3]);
        }
        __syncthreads();
    }

    float4 bb0 = *(const float4*)(bias + nb + 4 * tn);
    float4 bb1 = *(const float4*)(bias + nb + 64 + 4 * tn);
#pragma unroll
    for (int i = 0; i < 8; ++i) {
        float* crow = C + (size_t)(mb + 8 * tm + i) * N + nb;
        float2 p0 = unpk(acc[i][0]), p1 = unpk(acc[i][1]);
        float2 p2 = unpk(acc[i][2]), p3 = unpk(acc[i][3]);
        float4 o0; o0.x = p0.x + bb0.x; o0.y = p0.y + bb0.y; o0.z = p1.x + bb0.z; o0.w = p1.y + bb0.w;
        float4 o1; o1.x = p2.x + bb1.x; o1.y = p2.y + bb1.y; o1.z = p3.x + bb1.z; o1.w = p3.y + bb1.w;
        *(float4*)(crow + 4 * tn)      = o0;
        *(float4*)(crow + 64 + 4 * tn) = o1;
    }
}

// ---------------------------------------------------------------------------
// GRU recurrence: 32 clusters x 4 CTAs, 512 threads/CTA.
// Thread = (h_local 0..63) x (bp 0..3) x (ks 0..1).  Each thread: 1 hidden
// unit, 2 batches (bp, bp+4), half of k (ks).  Row stride 264, ks-half at
// +132 -> conflict-free LDS.128.  shfl_xor(1) merges the two k-halves.
// ---------------------------------------------------------------------------
#define RSTR 264
#define REC_W_FLOATS (192 * RSTR)
#define REC_SMEM ((192 * RSTR + 2 * 8 * RSTR) * 4)   // 219648 B

DEV_INLINE unsigned ctarank() { unsigned r; asm("mov.u32 %0, %%cluster_ctarank;" : "=r"(r)); return r; }
DEV_INLINE unsigned s2u(const void* p) {
    unsigned a;
    asm("{ .reg .u64 t; cvta.to.shared.u64 t, %1; cvt.u32.u64 %0, t; }" : "=r"(a) : "l"(p));
    return a;
}
DEV_INLINE unsigned mapa_(unsigned a, unsigned r) {
    unsigned o; asm("mapa.shared::cluster.u32 %0, %1, %2;" : "=r"(o) : "r"(a), "r"(r)); return o;
}
DEV_INLINE void st_cluster_u32(unsigned addr, unsigned v) {
    asm volatile("st.shared::cluster.u32 [%0], %1;" :: "r"(addr), "r"(v) : "memory");
}
DEV_INLINE void cl_arrive() { asm volatile("barrier.cluster.arrive.aligned;" ::: "memory"); }
DEV_INLINE void cl_wait()   { asm volatile("barrier.cluster.wait.aligned;"   ::: "memory"); }

__global__ __launch_bounds__(512, 1) void gru_rec(
    const float* __restrict__ xg, const float* __restrict__ W_hh,
    const float* __restrict__ b_hh, float* __restrict__ out_seq,
    float* __restrict__ hT, int layer0)
{
    extern __shared__ float smem[];
    float* w = smem;                        // [192 rows][264]  k in [0..127],[132..259]
    float* hbase = smem + REC_W_FLOATS;     // [2 bufs][8 batches][264]

    const int tid = threadIdx.x;
    const unsigned rank = ctarank();
    const int cid = blockIdx.x >> 2;        // cluster 0..31
    const int h_local = tid >> 3;           // 0..63
    const int bp = (tid >> 1) & 3;          // 0..3
    const int ks = tid & 1;                 // k-half
    const int h_glob = (int)rank * 64 + h_local;
    const int bsel = bp + 4 * ks;           // the batch this lane finalizes
    const int bglob = cid * 8 + bsel;
    const int hpoff = h_glob + ((h_glob >= 128) ? 4 : 0);  // h position in split row

    // Load W_hh slice: smem row g*64+h <- global row g*256 + rank*64 + h
    for (int i = tid; i < 192 * 64; i += 512) {
        int row = i >> 6, kk = (i & 63) * 4;
        int grow = (row >> 6) * 256 + (int)rank * 64 + (row & 63);
        float4 v = ((const float4*)W_hh)[(size_t)grow * 64 + (kk >> 2)];
        *(float4*)(w + row * RSTR + kk + ((kk >= 128) ? 4 : 0)) = v;
    }
    for (int i = tid; i < 8 * RSTR; i += 512) hbase[i] = 0.f;  // h buffer 0 = 0

    const float bh_r = b_hh[h_glob];
    const float bh_z = b_hh[256 + h_glob];
    const float bh_n = b_hh[512 + h_glob];

    __syncthreads();
    cl_arrive(); cl_wait();

    unsigned hbase_u = s2u(hbase);
    unsigned pb[4];
#pragma unroll
    for (int q = 0; q < 4; ++q) pb[q] = mapa_(hbase_u, (unsigned)q);

    const int ko = ks * 132;                // k-half offset in a row
    const float* wr = w + h_local * RSTR + ko;
    const float* wz = wr + 64 * RSTR;
    const float* wn = wr + 128 * RSTR;

    const float* xrow = xg + (size_t)bglob * TT * G3;
    float xr = xrow[h_glob], xz = xrow[256 + h_glob], xn = xrow[512 + h_glob];

    int p = 0;
    for (int t = 0; t < TT; ++t) {
        const float* h0r = hbase + (p * 8 + bp) * RSTR + ko;       // batch bp
        const float* h1r = h0r + 4 * RSTR;                          // batch bp+4

        ull ar0 = 0, az0 = 0, an0 = 0, ar1 = 0, az1 = 0, an1 = 0;
#pragma unroll 8
        for (int k4 = 0; k4 < 32; ++k4) {
            ulonglong2 wrv = *(const ulonglong2*)(wr + 4 * k4);
            ulonglong2 wzv = *(const ulonglong2*)(wz + 4 * k4);
            ulonglong2 wnv = *(const ulonglong2*)(wn + 4 * k4);
            ulonglong2 h0v = *(const ulonglong2*)(h0r + 4 * k4);
            ulonglong2 h1v = *(const ulonglong2*)(h1r + 4 * k4);
            ar0 = fma2(wrv.x, h0v.x, ar0); ar0 = fma2(wrv.y, h0v.y, ar0);
            az0 = fma2(wzv.x, h0v.x, az0); az0 = fma2(wzv.y, h0v.y, az0);
            an0 = fma2(wnv.x, h0v.x, an0); an0 = fma2(wnv.y, h0v.y, an0);
            ar1 = fma2(wrv.x, h1v.x, ar1); ar1 = fma2(wrv.y, h1v.y, ar1);
            az1 = fma2(wzv.x, h1v.x, az1); az1 = fma2(wzv.y, h1v.y, az1);
            an1 = fma2(wnv.x, h1v.x, an1); an1 = fma2(wnv.y, h1v.y, an1);
        }
        float2 s;
        s = unpk(ar0); float fr0 = s.x + s.y;
        s = unpk(az0); float fz0 = s.x + s.y;
        s = unpk(an0); float fn0 = s.x + s.y;
        s = unpk(ar1); float fr1 = s.x + s.y;
        s = unpk(az1); float fz1 = s.x + s.y;
        s = unpk(an1); float fn1 = s.x + s.y;

        // merge the two k-halves (partner lane differs in bit 0)
        fr0 += __shfl_xor_sync(0xffffffffu, fr0, 1);
        fz0 += __shfl_xor_sync(0xffffffffu, fz0, 1);
        fn0 += __shfl_xor_sync(0xffffffffu, fn0, 1);
        fr1 += __shfl_xor_sync(0xffffffffu, fr1, 1);
        fz1 += __shfl_xor_sync(0xffffffffu, fz1, 1);
        fn1 += __shfl_xor_sync(0xffffffffu, fn1, 1);

        float hr = ks ? fr1 : fr0;
        float hz = ks ? fz1 : fz0;
        float hn = ks ? fn1 : fn0;

        float hp = hbase[(p * 8 + bsel) * RSTR + hpoff];

        float r = 1.f / (1.f + __expf(-(xr + bh_r + hr)));
        float z = 1.f / (1.f + __expf(-(xz + bh_z + hz)));
        float n = tanhf(xn + r * (hn + bh_n));
        float hnew = (1.f - z) * n + z * hp;

        // broadcast to all 4 cluster CTAs (buffer 1-p)
        unsigned off = (unsigned)(((1 - p) * 8 + bsel) * RSTR + hpoff) * 4u;
        unsigned hb = __float_as_uint(hnew);
        st_cluster_u32(pb[0] + off, hb);
        st_cluster_u32(pb[1] + off, hb);
        st_cluster_u32(pb[2] + off, hb);
        st_cluster_u32(pb[3] + off, hb);

        cl_arrive();

        // overlapped with barrier: next-x prefetch + output store
        if (t + 1 < TT) {
            const float* xp = xrow + (size_t)(t + 1) * G3;
            xr = xp[h_glob]; xz = xp[256 + h_glob]; xn = xp[512 + h_glob];
        }
        if (layer0) {
            out_seq[((size_t)bglob * TT + t) * HH + h_glob] = hnew;
        } else if (t == TT - 1) {
            hT[bglob * HH + h_glob] = hnew;
        }

        cl_wait();
        p ^= 1;
    }
}

// ---------------------------------------------------------------------------
// Launch helpers
// ---------------------------------------------------------------------------
static void launch_rec(const float* xg, const float* Whh, const float* bhh,
                       float* oseq, float* hT, int layer0)
{
    cudaFuncSetAttribute(gru_rec, cudaFuncAttributeMaxDynamicSharedMemorySize, REC_SMEM);
    cudaLaunchConfig_t cfg = {};
    cfg.gridDim = dim3(128, 1, 1);
    cfg.blockDim = dim3(512, 1, 1);
    cfg.dynamicSmemBytes = REC_SMEM;
    cfg.stream = 0;
    cudaLaunchAttribute at[1];
    at[0].id = cudaLaunchAttributeClusterDimension;
    at[0].val.clusterDim.x = 4;
    at[0].val.clusterDim.y = 1;
    at[0].val.clusterDim.z = 1;
    cfg.attrs = at;
    cfg.numAttrs = 1;
    cudaLaunchKernelEx(&cfg, gru_rec, xg, Whh, bhh, oseq, hT, layer0);
}

extern "C" void kernel_launch(void* const* d_in, const int* in_sizes, int n_in,
                              void* d_out, int out_size)
{
    const float* x     = (const float*)d_in[0];
    const float* W_ih0 = (const float*)d_in[1];
    const float* W_hh0 = (const float*)d_in[2];
    const float* b_ih0 = (const float*)d_in[3];
    const float* b_hh0 = (const float*)d_in[4];
    const float* W_ih1 = (const float*)d_in[5];
    const float* W_hh1 = (const float*)d_in[6];
    const float* b_ih1 = (const float*)d_in[7];
    const float* b_hh1 = (const float*)d_in[8];
    const float* fc_W  = (const float*)d_in[9];
    const float* fc_b  = (const float*)d_in[10];
    float* out = (float*)d_out;

    float *xg, *o0, *hT, *xp, *wp;
    cudaGetSymbolAddress((void**)&xg, g_xg);
    cudaGetSymbolAddress((void**)&o0, g_out0);
    cudaGetSymbolAddress((void**)&hT, g_hT);
    cudaGetSymbolAddress((void**)&xp, g_xpad);
    cudaGetSymbolAddress((void**)&wp, g_wpad);

    const int M = BB * TT;  // 131072

    // 0) pad x and W_ih0 to K=80 so the vector GEMM path applies
    pad_k75<<<(M * KP + 255) / 256, 256>>>(x, xp, M);
    pad_k75<<<(G3 * KP + 255) / 256, 256>>>(W_ih0, wp, G3);
    // 1) xg0 = xpad @ wpad^T + b_ih0   (K = 80)
    gemm_tn_bias<<<dim3(M / 128, G3 / 128), 256>>>(xp, wp, b_ih0, xg, M, G3, KP);
    // 2) layer-0 recurrence -> out0 sequence
    launch_rec(xg, W_hh0, b_hh0, o0, nullptr, 1);
    // 3) xg1 = out0 @ W_ih1^T + b_ih1  (K = 256)
    gemm_tn_bias<<<dim3(M / 128, G3 / 128), 256>>>(o0, W_ih1, b_ih1, xg, M, G3, 256);
    // 4) layer-1 recurrence -> final hidden
    launch_rec(xg, W_hh1, b_hh1, nullptr, hT, 0);
    // 5) embedding = hT @ fc_W^T + fc_b
    gemm_tn_bias<<<dim3(BB / 128, HH / 128), 256>>>(hT, fc_W, fc_b, out, BB, HH, HH);
}